// round 3
// baseline (speedup 1.0000x reference)
#include <cuda_runtime.h>
#include <cuda_bf16.h>

// Fixed shapes
#define H_DIM   1024
#define N_DIM   64
#define SEQ_L   2048
#define LHALF   1024               // l-range per block
#define CHUNK   32                 // l-values per (c, q) thread
#define NCH     (LHALF / CHUNK)    // 32 chunks per block

typedef unsigned long long ull;
__device__ __forceinline__ ull pack2(float lo, float hi) {
    ull r; asm("mov.b64 %0, {%1, %2};" : "=l"(r) : "f"(lo), "f"(hi)); return r;
}
__device__ __forceinline__ ull fma2(ull a, ull b, ull c) {
    ull d; asm("fma.rn.f32x2 %0, %1, %2, %3;" : "=l"(d) : "l"(a), "l"(b), "l"(c)); return d;
}
__device__ __forceinline__ ull mul2(ull a, ull b) {
    ull d; asm("mul.rn.f32x2 %0, %1, %2;" : "=l"(d) : "l"(a), "l"(b)); return d;
}
__device__ __forceinline__ ull add2(ull a, ull b) {
    ull d; asm("add.rn.f32x2 %0, %1, %2;" : "=l"(d) : "l"(a), "l"(b)); return d;
}

// ============================================================================
// One block per (h, l-half). 128 threads (4 warps), residency pinned to 7/SM
// via launch_bounds + dummy dynamic smem -> grid 2048 = exactly 2 full waves.
//
// Phase 1: threads = (n 0..63, sub 0..1). Per n: discretized params; seeds
//   (y0, y1) for 16 chunks (stride r^32) starting at l = 512*(2*half+sub).
// Phase 2: threads = (chunk c 0..31, quarter q 0..3). Packed stride-2
//   recurrence over 32 l, 16 n per quarter (2 interleaved streams).
// Phase 3: 4-way quarter reduction in smem; warp 0 stores.
// ============================================================================
__global__ void __launch_bounds__(128, 7) ssk_fused(
    const float* __restrict__ Cri, const float* __restrict__ logdt,
    const float* __restrict__ Bri, const float* __restrict__ invAr,
    const float* __restrict__ Aim, float* __restrict__ out)
{
    __shared__ float2 s_seed[N_DIM * NCH];   // 16KB, [n][c ^ (n&31)]
    __shared__ float4 s_par[N_DIM];          // 1KB, (p1, q1, p2, q2)

    const int tx   = threadIdx.x;            // 0..127
    const int h    = blockIdx.x >> 1;
    const int half = blockIdx.x & 1;

    // ---------------- Phase 1: params + seeds ----------------
    {
        const int n   = tx & 63;
        const int sub = tx >> 6;
        const int idx = h * N_DIM + n;

        float cr = Cri[2 * idx], ci = Cri[2 * idx + 1];
        float br = Bri[2 * idx], bi = Bri[2 * idx + 1];
        float dt = __expf(logdt[h]);
        float Ar = -__expf(invAr[idx]);
        float Ai = Aim[idx];

        float zr = Ar * dt, zi = Ai * dt;
        float dr = 1.0f - 0.5f * zr, di = -0.5f * zi;
        float inv = 1.0f / (dr * dr + di * di);

        float bcr = br * cr - bi * ci;
        float bci = br * ci + bi * cr;
        float s = 2.0f * dt * inv;
        float ctr = (bcr * dr + bci * di) * s;   // Ct2 = 2*B*C*dt/den
        float cti = (bci * dr - bcr * di) * s;

        float nr = 1.0f + 0.5f * zr, ni = 0.5f * zi;
        float rr = (nr * dr + ni * di) * inv;    // r, |r| < 1
        float ri = (ni * dr - nr * di) * inv;

        float m2  = rr * rr + ri * ri;           // |r|^2
        float r2r = rr * rr - ri * ri;
        float r2i = 2.0f * rr * ri;
        if (sub == 0)
            s_par[n] = make_float4(2.0f * rr, -m2, 2.0f * r2r, -(m2 * m2));

        // s32 = r^32 : 4 squarings of r^2
        float sr = r2r, si = r2i;
#pragma unroll
        for (int i = 0; i < 4; i++) {
            float tr = sr * sr - si * si;
            si = 2.0f * sr * si;
            sr = tr;
        }
        // p512 = (r^32)^16 : 4 squarings
        float pr = sr, pi = si;
#pragma unroll
        for (int i = 0; i < 4; i++) {
            float tr = pr * pr - pi * pi;
            pi = 2.0f * pr * pi;
            pr = tr;
        }
        // m = r^(512*t), t = 2*half + sub  (0..3)
        const int t = 2 * half + sub;
        float mr = 1.0f, mi = 0.0f;
        if (t & 1) { mr = pr; mi = pi; }
        float pqr = pr * pr - pi * pi;           // r^1024
        float pqi = 2.0f * pr * pi;
        if (t & 2) {
            float tr = mr * pqr - mi * pqi;
            mi = mr * pqi + mi * pqr;
            mr = tr;
        }
        float wr = ctr * mr - cti * mi;          // w = Ct2 * r^(512*t)
        float wi = ctr * mi + cti * mr;

        const int cb = sub * 16;
#pragma unroll 1
        for (int i = 0; i < 16; i++) {
            float y1 = wr * rr - wi * ri;        // Re(w * r)
            s_seed[n * NCH + ((cb + i) ^ (n & 31))] = make_float2(wr, y1);
            float tr = wr * sr - wi * si;        // w *= r^32
            wi = wr * si + wi * sr;
            wr = tr;
        }
    }
    __syncthreads();

    // ---------------- Phase 2: packed recurrence ----------------
    const int c = tx & 31;                       // chunk (lane)
    const int q = tx >> 5;                       // quarter (warp)

    ull acc[CHUNK / 2];
#pragma unroll
    for (int k = 0; k < CHUNK / 2; k++) acc[k] = 0ull;

    const int n0 = q * 16;
#pragma unroll 1
    for (int np = 0; np < 8; np++) {
        const int na = n0 + 2 * np;
        const int nb = na + 1;

        float4 pa = s_par[na];
        float4 pb = s_par[nb];
        float2 sa = s_seed[na * NCH + (c ^ (na & 31))];
        float2 sb = s_seed[nb * NCH + (c ^ (nb & 31))];

        // reconstruct y2, y3 via stride-1 recurrence
        float y2a = fmaf(pa.x, sa.y, pa.y * sa.x);
        float y3a = fmaf(pa.x, y2a, pa.y * sa.y);
        float y2b = fmaf(pb.x, sb.y, pb.y * sb.x);
        float y3b = fmaf(pb.x, y2b, pb.y * sb.y);

        ull p2a = pack2(pa.z, pa.z), q2a = pack2(pa.w, pa.w);
        ull p2b = pack2(pb.z, pb.z), q2b = pack2(pb.w, pb.w);

        ull vpA = pack2(sa.x, sa.y), vcA = pack2(y2a, y3a);
        ull vpB = pack2(sb.x, sb.y), vcB = pack2(y2b, y3b);

        acc[0] = add2(acc[0], add2(vpA, vpB));
        acc[1] = add2(acc[1], add2(vcA, vcB));

#pragma unroll
        for (int k = 2; k < CHUNK / 2; k++) {
            ull nA = fma2(p2a, vcA, mul2(q2a, vpA));
            ull nB = fma2(p2b, vcB, mul2(q2b, vpB));
            acc[k] = add2(acc[k], add2(nA, nB));
            vpA = vcA; vcA = nA;
            vpB = vcB; vcB = nB;
        }
    }

    // ---------------- Phase 3: quarter reduction + store ----------------
    __syncthreads();                              // seeds no longer needed
    ull* red = (ull*)s_seed;                      // reuse 16KB region

    if (q >= 2) {
#pragma unroll
        for (int k = 0; k < CHUNK / 2; k++)
            red[k * 64 + (q - 2) * 32 + c] = acc[k];
    }
    __syncthreads();
    if (q < 2) {
#pragma unroll
        for (int k = 0; k < CHUNK / 2; k++)
            acc[k] = add2(acc[k], red[k * 64 + q * 32 + c]);
    }
    __syncthreads();
    if (q == 1) {
#pragma unroll
        for (int k = 0; k < CHUNK / 2; k++)
            red[k * 32 + c] = acc[k];
    }
    __syncthreads();
    if (q == 0) {
#pragma unroll
        for (int k = 0; k < CHUNK / 2; k++)
            acc[k] = add2(acc[k], red[k * 32 + c]);

        ulonglong2* op = (ulonglong2*)(out + (size_t)h * SEQ_L
                                       + half * LHALF + c * CHUNK);
#pragma unroll
        for (int k = 0; k < CHUNK / 4; k++)
            op[k] = make_ulonglong2(acc[2 * k], acc[2 * k + 1]);
    }
}

extern "C" void kernel_launch(void* const* d_in, const int* in_sizes, int n_in,
                              void* d_out, int out_size)
{
    const float* Cri   = (const float*)d_in[0];   // (1, H, N, 2)
    const float* logdt = (const float*)d_in[1];   // (H,)
    const float* Bri   = (const float*)d_in[2];   // (H, N, 2) (n_ssm == H)
    const float* invAr = (const float*)d_in[3];   // (H, N)
    const float* Aim   = (const float*)d_in[4];   // (H, N)
    float* out = (float*)d_out;                   // (1, H, L)

    // 12KB dummy dynamic smem: per-CTA footprint ~30KB -> exactly 7 CTAs/SM,
    // conc = 7*148 = 1036 -> grid 2048 = 2 near-full waves.
    ssk_fused<<<H_DIM * 2, 128, 12 * 1024>>>(Cri, logdt, Bri, invAr, Aim, out);
}

// round 4
// speedup vs baseline: 1.0688x; 1.0688x over previous
#include <cuda_runtime.h>
#include <cuda_bf16.h>

// Fixed shapes
#define H_DIM   1024
#define N_DIM   64
#define SEQ_L   2048
#define LHALF   1024               // l-range per block
#define CHUNK   32                 // l-values per (c, q) thread
#define NCH     (LHALF / CHUNK)    // 32 chunks per block

typedef unsigned long long ull;
__device__ __forceinline__ ull pack2(float lo, float hi) {
    ull r; asm("mov.b64 %0, {%1, %2};" : "=l"(r) : "f"(lo), "f"(hi)); return r;
}
__device__ __forceinline__ ull fma2(ull a, ull b, ull c) {
    ull d; asm("fma.rn.f32x2 %0, %1, %2, %3;" : "=l"(d) : "l"(a), "l"(b), "l"(c)); return d;
}
__device__ __forceinline__ ull mul2(ull a, ull b) {
    ull d; asm("mul.rn.f32x2 %0, %1, %2;" : "=l"(d) : "l"(a), "l"(b)); return d;
}
__device__ __forceinline__ ull add2(ull a, ull b) {
    ull d; asm("add.rn.f32x2 %0, %1, %2;" : "=l"(d) : "l"(a), "l"(b)); return d;
}

// ============================================================================
// One block per (h, l-half). 128 threads (4 warps), residency pinned to 7/SM
// via launch_bounds + dummy dynamic smem -> grid 2048 = exactly 2 full waves.
//
// Phase 1: threads = (n 0..63, sub 0..1). Per n: discretized params; seeds
//   (y0, y1) for 16 chunks (stride r^32) starting at l = 512*(2*half+sub).
// Phase 2: threads = (chunk c 0..31, quarter q 0..3). Packed stride-2
//   recurrence over 32 l, 16 n per quarter (2 interleaved streams).
// Phase 3: 4-way quarter reduction in smem; warp 0 stores.
// ============================================================================
__global__ void __launch_bounds__(128, 7) ssk_fused(
    const float* __restrict__ Cri, const float* __restrict__ logdt,
    const float* __restrict__ Bri, const float* __restrict__ invAr,
    const float* __restrict__ Aim, float* __restrict__ out)
{
    __shared__ float2 s_seed[N_DIM * NCH];   // 16KB, [n][c ^ (n&31)]
    __shared__ float4 s_par[N_DIM];          // 1KB, (p1, q1, p2, q2)

    const int tx   = threadIdx.x;            // 0..127
    const int h    = blockIdx.x >> 1;
    const int half = blockIdx.x & 1;

    // ---------------- Phase 1: params + seeds ----------------
    {
        const int n   = tx & 63;
        const int sub = tx >> 6;
        const int idx = h * N_DIM + n;

        float cr = Cri[2 * idx], ci = Cri[2 * idx + 1];
        float br = Bri[2 * idx], bi = Bri[2 * idx + 1];
        float dt = __expf(logdt[h]);
        float Ar = -__expf(invAr[idx]);
        float Ai = Aim[idx];

        float zr = Ar * dt, zi = Ai * dt;
        float dr = 1.0f - 0.5f * zr, di = -0.5f * zi;
        float inv = 1.0f / (dr * dr + di * di);

        float bcr = br * cr - bi * ci;
        float bci = br * ci + bi * cr;
        float s = 2.0f * dt * inv;
        float ctr = (bcr * dr + bci * di) * s;   // Ct2 = 2*B*C*dt/den
        float cti = (bci * dr - bcr * di) * s;

        float nr = 1.0f + 0.5f * zr, ni = 0.5f * zi;
        float rr = (nr * dr + ni * di) * inv;    // r, |r| < 1
        float ri = (ni * dr - nr * di) * inv;

        float m2  = rr * rr + ri * ri;           // |r|^2
        float r2r = rr * rr - ri * ri;
        float r2i = 2.0f * rr * ri;
        if (sub == 0)
            s_par[n] = make_float4(2.0f * rr, -m2, 2.0f * r2r, -(m2 * m2));

        // s32 = r^32 : 4 squarings of r^2
        float sr = r2r, si = r2i;
#pragma unroll
        for (int i = 0; i < 4; i++) {
            float tr = sr * sr - si * si;
            si = 2.0f * sr * si;
            sr = tr;
        }
        // p512 = (r^32)^16 : 4 squarings
        float pr = sr, pi = si;
#pragma unroll
        for (int i = 0; i < 4; i++) {
            float tr = pr * pr - pi * pi;
            pi = 2.0f * pr * pi;
            pr = tr;
        }
        // m = r^(512*t), t = 2*half + sub  (0..3)
        const int t = 2 * half + sub;
        float mr = 1.0f, mi = 0.0f;
        if (t & 1) { mr = pr; mi = pi; }
        float pqr = pr * pr - pi * pi;           // r^1024
        float pqi = 2.0f * pr * pi;
        if (t & 2) {
            float tr = mr * pqr - mi * pqi;
            mi = mr * pqi + mi * pqr;
            mr = tr;
        }
        float wr = ctr * mr - cti * mi;          // w = Ct2 * r^(512*t)
        float wi = ctr * mi + cti * mr;

        const int cb = sub * 16;
#pragma unroll 1
        for (int i = 0; i < 16; i++) {
            float y1 = wr * rr - wi * ri;        // Re(w * r)
            s_seed[n * NCH + ((cb + i) ^ (n & 31))] = make_float2(wr, y1);
            float tr = wr * sr - wi * si;        // w *= r^32
            wi = wr * si + wi * sr;
            wr = tr;
        }
    }
    __syncthreads();

    // ---------------- Phase 2: packed recurrence ----------------
    const int c = tx & 31;                       // chunk (lane)
    const int q = tx >> 5;                       // quarter (warp)

    ull acc[CHUNK / 2];
#pragma unroll
    for (int k = 0; k < CHUNK / 2; k++) acc[k] = 0ull;

    const int n0 = q * 16;
#pragma unroll 1
    for (int np = 0; np < 8; np++) {
        const int na = n0 + 2 * np;
        const int nb = na + 1;

        float4 pa = s_par[na];
        float4 pb = s_par[nb];
        float2 sa = s_seed[na * NCH + (c ^ (na & 31))];
        float2 sb = s_seed[nb * NCH + (c ^ (nb & 31))];

        // reconstruct y2, y3 via stride-1 recurrence
        float y2a = fmaf(pa.x, sa.y, pa.y * sa.x);
        float y3a = fmaf(pa.x, y2a, pa.y * sa.y);
        float y2b = fmaf(pb.x, sb.y, pb.y * sb.x);
        float y3b = fmaf(pb.x, y2b, pb.y * sb.y);

        ull p2a = pack2(pa.z, pa.z), q2a = pack2(pa.w, pa.w);
        ull p2b = pack2(pb.z, pb.z), q2b = pack2(pb.w, pb.w);

        ull vpA = pack2(sa.x, sa.y), vcA = pack2(y2a, y3a);
        ull vpB = pack2(sb.x, sb.y), vcB = pack2(y2b, y3b);

        acc[0] = add2(acc[0], add2(vpA, vpB));
        acc[1] = add2(acc[1], add2(vcA, vcB));

#pragma unroll
        for (int k = 2; k < CHUNK / 2; k++) {
            ull nA = fma2(p2a, vcA, mul2(q2a, vpA));
            ull nB = fma2(p2b, vcB, mul2(q2b, vpB));
            acc[k] = add2(acc[k], add2(nA, nB));
            vpA = vcA; vcA = nA;
            vpB = vcB; vcB = nB;
        }
    }

    // ---------------- Phase 3: quarter reduction + store ----------------
    __syncthreads();                              // seeds no longer needed
    ull* red = (ull*)s_seed;                      // reuse 16KB region

    if (q >= 2) {
#pragma unroll
        for (int k = 0; k < CHUNK / 2; k++)
            red[k * 64 + (q - 2) * 32 + c] = acc[k];
    }
    __syncthreads();
    if (q < 2) {
#pragma unroll
        for (int k = 0; k < CHUNK / 2; k++)
            acc[k] = add2(acc[k], red[k * 64 + q * 32 + c]);
    }
    __syncthreads();
    if (q == 1) {
#pragma unroll
        for (int k = 0; k < CHUNK / 2; k++)
            red[k * 32 + c] = acc[k];
    }
    __syncthreads();
    if (q == 0) {
#pragma unroll
        for (int k = 0; k < CHUNK / 2; k++)
            acc[k] = add2(acc[k], red[k * 32 + c]);

        ulonglong2* op = (ulonglong2*)(out + (size_t)h * SEQ_L
                                       + half * LHALF + c * CHUNK);
#pragma unroll
        for (int k = 0; k < CHUNK / 4; k++)
            op[k] = make_ulonglong2(acc[2 * k], acc[2 * k + 1]);
    }
}

extern "C" void kernel_launch(void* const* d_in, const int* in_sizes, int n_in,
                              void* d_out, int out_size)
{
    const float* Cri   = (const float*)d_in[0];   // (1, H, N, 2)
    const float* logdt = (const float*)d_in[1];   // (H,)
    const float* Bri   = (const float*)d_in[2];   // (H, N, 2) (n_ssm == H)
    const float* invAr = (const float*)d_in[3];   // (H, N)
    const float* Aim   = (const float*)d_in[4];   // (H, N)
    float* out = (float*)d_out;                   // (1, H, L)

    // 12KB dummy dynamic smem: per-CTA footprint ~30KB -> exactly 7 CTAs/SM,
    // conc = 7*148 = 1036 -> grid 2048 = 2 near-full waves.
    ssk_fused<<<H_DIM * 2, 128, 12 * 1024>>>(Cri, logdt, Bri, invAr, Aim, out);
}